// round 16
// baseline (speedup 1.0000x reference)
#include <cuda_runtime.h>
#include <cuda_bf16.h>
#include <cstdint>

#define NROWS 65536
#define DDIM  512
#define EDIM  256
#define TDIM  128
#define KDIM  896   // D + E + T
#define NPROTO 5

// Wq in bf16 (0.9 MB) — device global per harness rules
__device__ __align__(16) __nv_bfloat16 g_B[(size_t)DDIM * KDIM];

__device__ __forceinline__ uint32_t pack2(float a, float b) {
    __nv_bfloat162 h = __floats2bfloat162_rn(a, b);   // a -> low half
    return *reinterpret_cast<uint32_t*>(&h);
}
__device__ __forceinline__ float2 unpack2(uint32_t u) {
    return __bfloat1622float2(*reinterpret_cast<__nv_bfloat162*>(&u));
}

// ---------------------------------------------------------------------------
// Pre-convert Wq (fp32) -> g_B (bf16), row-major [512][896]
// ---------------------------------------------------------------------------
__global__ void convB_kernel(const float* __restrict__ Wq) {
    int i = blockIdx.x * 256 + threadIdx.x;           // 114688 float4 items
    float4 v = reinterpret_cast<const float4*>(Wq)[i];
    reinterpret_cast<uint2*>(g_B)[i] = make_uint2(pack2(v.x, v.y), pack2(v.z, v.w));
}

// ---------------------------------------------------------------------------
// FUSED kernel: per CTA of 512 threads: GEMM tile M=64 x N=512 (full rows),
// then in-kernel epilogue on those 64 rows (y staged via smem, no g_y).
// ---------------------------------------------------------------------------
constexpr int BM = 64, BN = 512;
constexpr int A_TILE = BM * 64;               // 4 KB
constexpr int B_TILE = BN * 64;               // 32 KB
constexpr int STAGEB = A_TILE + B_TILE;       // 36 KB per stage
constexpr int FUSED_SMEM = 2 * STAGEB;        // 73728 B (>= 64 KB staging)

__device__ __forceinline__ void cp16(uint32_t saddr, const void* gaddr) {
    asm volatile("cp.async.cg.shared.global [%0], [%1], 16;\n" :: "r"(saddr), "l"(gaddr));
}
__device__ __forceinline__ int swz(int r, int c) {            // GEMM tiles
    return r * 64 + ((c ^ ((r >> 1) & 3)) << 4);
}
__device__ __forceinline__ uint32_t lds32(const char* base, int r, int c, int t) {
    return *reinterpret_cast<const uint32_t*>(base + swz(r, c) + 4 * t);
}
__device__ __forceinline__ int sy(int r, int off) {           // y staging (1024B rows)
    return r * 1024 + (off ^ ((r & 7) << 4));
}

__device__ __forceinline__ float wredsum(float x) {
    #pragma unroll
    for (int o = 16; o > 0; o >>= 1) x += __shfl_xor_sync(0xffffffffu, x, o);
    return x;
}
__device__ __forceinline__ float clampf(float x, float a) { return fminf(fmaxf(x, -a), a); }
__device__ __forceinline__ float4 c4(float4 v, float a) {
    return make_float4(clampf(v.x,a), clampf(v.y,a), clampf(v.z,a), clampf(v.w,a));
}

__global__ void __launch_bounds__(512, 1)
fused_kernel(const float* __restrict__ raw, const float* __restrict__ edge,
             const float* __restrict__ te,  const float* __restrict__ protos,
             const float* __restrict__ bq,  const float* __restrict__ Wg,
             const float* __restrict__ bg,  const float* __restrict__ gam,
             const float* __restrict__ bet, const float* __restrict__ temperature,
             float* __restrict__ out) {
    extern __shared__ char sm[];
    const int tid  = threadIdx.x;
    const int m0   = blockIdx.x * BM;
    const int warp = tid >> 5, lane = tid & 31;
    const int wm   = warp & 1, wn = warp >> 1;   // 2 warps along M, 8 along N
    const int g    = lane >> 2, t = lane & 3;

    float acc[2][8][4];
    #pragma unroll
    for (int mi = 0; mi < 2; mi++)
        #pragma unroll
        for (int ni = 0; ni < 8; ni++)
            #pragma unroll
            for (int j = 0; j < 4; j++) acc[mi][ni][j] = 0.f;

    auto asrc = [&](int kt, const float*& base, int& stride, int& col0) {
        if (kt < 16)      { base = raw;  stride = DDIM; col0 = kt * 32; }
        else if (kt < 24) { base = edge; stride = EDIM; col0 = (kt - 16) * 32; }
        else              { base = te;   stride = TDIM; col0 = (kt - 24) * 32; }
    };
    float4 vA;
    auto ldgA = [&](int kt) {               // 512 items: r = tid>>3, c4 = tid&7
        const float* base; int stride, col0;
        asrc(kt, base, stride, col0);
        int r = tid >> 3, c4 = tid & 7;
        vA = *reinterpret_cast<const float4*>(
            base + (size_t)(m0 + r) * stride + col0 + c4 * 4);
    };
    auto stsA = [&](char* As) {
        int r = tid >> 3, c4 = tid & 7;
        *reinterpret_cast<uint2*>(As + swz(r, c4 >> 1) + (c4 & 1) * 8) =
            make_uint2(pack2(vA.x, vA.y), pack2(vA.z, vA.w));
    };
    auto cpB = [&](int kt, char* Bs) {
        const __nv_bfloat16* gb = g_B + kt * 32;
        #pragma unroll
        for (int i = 0; i < 4; i++) {
            int idx = tid + i * 512;        // 2048 items: r = idx>>2, chunk = idx&3
            int r = idx >> 2, c = idx & 3;
            cp16((uint32_t)__cvta_generic_to_shared(Bs + swz(r, c)),
                 gb + (size_t)r * KDIM + c * 8);
        }
        asm volatile("cp.async.commit_group;\n");
    };

    // ---- GEMM mainloop (validated skeleton) ----
    ldgA(0);
    stsA(sm);
    cpB(0, sm + A_TILE);
    ldgA(1);

    for (int kt = 0; kt < 28; kt++) {
        char* curA = sm + (kt & 1) * STAGEB;
        char* curB = curA + A_TILE;
        if (kt < 27) {
            char* nxtA = sm + ((kt + 1) & 1) * STAGEB;
            stsA(nxtA);
            cpB(kt + 1, nxtA + A_TILE);
            if (kt < 26) ldgA(kt + 2);
            asm volatile("cp.async.wait_group 1;\n");
        } else {
            asm volatile("cp.async.wait_group 0;\n");
        }
        __syncthreads();

        #pragma unroll
        for (int ks = 0; ks < 2; ks++) {
            const int kc = ks * 2;
            uint32_t a[2][4], b[8][2];
            #pragma unroll
            for (int mi = 0; mi < 2; mi++) {
                int r0 = wm * 32 + mi * 16 + g;
                a[mi][0] = lds32(curA, r0,     kc,     t);
                a[mi][1] = lds32(curA, r0 + 8, kc,     t);
                a[mi][2] = lds32(curA, r0,     kc + 1, t);
                a[mi][3] = lds32(curA, r0 + 8, kc + 1, t);
            }
            #pragma unroll
            for (int ni = 0; ni < 8; ni++) {
                int n = wn * 64 + ni * 8 + g;
                b[ni][0] = lds32(curB, n, kc,     t);
                b[ni][1] = lds32(curB, n, kc + 1, t);
            }
            #pragma unroll
            for (int mi = 0; mi < 2; mi++)
                #pragma unroll
                for (int ni = 0; ni < 8; ni++) {
                    float* c = acc[mi][ni];
                    asm volatile(
                        "mma.sync.aligned.m16n8k16.row.col.f32.bf16.bf16.f32 "
                        "{%0,%1,%2,%3}, {%4,%5,%6,%7}, {%8,%9}, {%0,%1,%2,%3};\n"
                        : "+f"(c[0]), "+f"(c[1]), "+f"(c[2]), "+f"(c[3])
                        : "r"(a[mi][0]), "r"(a[mi][1]), "r"(a[mi][2]), "r"(a[mi][3]),
                          "r"(b[ni][0]), "r"(b[ni][1]));
                }
        }
        __syncthreads();
    }

    // ---- stage y (bf16) into smem: 64 rows x 1024 B, row-XOR swizzled ----
    char* stg = sm;
    #pragma unroll
    for (int mi = 0; mi < 2; mi++) {
        int rb = wm * 32 + mi * 16 + g;
        #pragma unroll
        for (int ni = 0; ni < 8; ni++) {
            int off = wn * 128 + ni * 16 + t * 4;
            *reinterpret_cast<uint32_t*>(stg + sy(rb,     off)) = pack2(acc[mi][ni][0], acc[mi][ni][1]);
            *reinterpret_cast<uint32_t*>(stg + sy(rb + 8, off)) = pack2(acc[mi][ni][2], acc[mi][ni][3]);
        }
    }
    __syncthreads();

    // ---- epilogue: each warp handles 4 rows (warp-per-row, validated R15) ----
    const float4* bq4 = reinterpret_cast<const float4*>(bq);
    const float4* g4  = reinterpret_cast<const float4*>(gam);
    const float4* b4  = reinterpret_cast<const float4*>(bet);
    const float4* w4  = reinterpret_cast<const float4*>(Wg);
    const float tmp   = fminf(fmaxf(temperature[0], 0.5f), 5.f) + 1e-4f;
    const float bg0   = bg[0];

    for (int it = 0; it < 4; it++) {
        const int rr  = warp * 4 + it;           // 0..63
        const int row = m0 + rr;
        const size_t base4 = (size_t)row * (DDIM / 4);
        const float4* r4p = reinterpret_cast<const float4*>(raw) + base4;
        const uint4*  p4p = reinterpret_cast<const uint4*>(protos) + (size_t)row * (NPROTO * DDIM / 4);

        // LN1 input: y + bq (y from smem staging)
        float4 yv[4];
        float s0 = 0.f, s1 = 0.f;
        #pragma unroll
        for (int j = 0; j < 4; j++) {
            uint2 u = *reinterpret_cast<const uint2*>(stg + sy(rr, 8 * lane + 256 * j));
            float2 lo = unpack2(u.x), hi = unpack2(u.y);
            float4 b = bq4[lane + 32 * j];
            float4 v = make_float4(lo.x + b.x, lo.y + b.y, hi.x + b.z, hi.y + b.w);
            yv[j] = v;
            s0 += v.x + v.y + v.z + v.w;
            s1 += v.x*v.x + v.y*v.y + v.z*v.z + v.w*v.w;
        }
        s0 = wredsum(s0); s1 = wredsum(s1);
        float mean = s0 * (1.f / DDIM);
        float rstd = rsqrtf(s1 * (1.f / DDIM) - mean * mean + 1e-6f);

        // q = tanh(LN(y))
        float4 qv[4];
        float sqq = 0.f;
        #pragma unroll
        for (int j = 0; j < 4; j++) {
            float4 gm = g4[lane + 32 * j], bt = b4[lane + 32 * j];
            float4 q;
            q.x = tanhf((yv[j].x - mean) * rstd * gm.x + bt.x);
            q.y = tanhf((yv[j].y - mean) * rstd * gm.y + bt.y);
            q.z = tanhf((yv[j].z - mean) * rstd * gm.z + bt.z);
            q.w = tanhf((yv[j].w - mean) * rstd * gm.w + bt.w);
            qv[j] = q;
            sqq += q.x*q.x + q.y*q.y + q.z*q.z + q.w*q.w;
        }

        // prototypes: norms + dots, kept as bf16x2 regs
        uint32_t pkb[NPROTO][8];
        float spp[NPROTO], sqp[NPROTO];
        #pragma unroll
        for (int k = 0; k < NPROTO; k++) {
            float app = 0.f, aqp = 0.f;
            #pragma unroll
            for (int j = 0; j < 4; j++) {
                uint4 u = p4p[k * (DDIM / 4) + lane + 32 * j];
                float4 v = make_float4(__uint_as_float(u.x), __uint_as_float(u.y),
                                       __uint_as_float(u.z), __uint_as_float(u.w));
                pkb[k][j * 2]     = pack2(v.x, v.y);
                pkb[k][j * 2 + 1] = pack2(v.z, v.w);
                float4 c = c4(v, 20.f);
                app += c.x*c.x + c.y*c.y + c.z*c.z + c.w*c.w;
                aqp += qv[j].x*c.x + qv[j].y*c.y + qv[j].z*c.z + qv[j].w*c.w;
            }
            spp[k] = app; sqp[k] = aqp;
        }
        sqq = wredsum(sqq);
        #pragma unroll
        for (int k = 0; k < NPROTO; k++) { spp[k] = wredsum(spp[k]); sqp[k] = wredsum(sqp[k]); }

        // cosine -> softmax (K=5)
        float qn = fmaxf(sqrtf(sqq), 1e-6f);
        float sim[NPROTO], mx = -1e30f;
        #pragma unroll
        for (int k = 0; k < NPROTO; k++) {
            float pn = fmaxf(sqrtf(spp[k]), 1e-6f);
            sim[k] = clampf(sqp[k] / (qn * pn), 15.f) / tmp;
            mx = fmaxf(mx, sim[k]);
        }
        float den = 0.f;
        #pragma unroll
        for (int k = 0; k < NPROTO; k++) { sim[k] = __expf(sim[k] - mx); den += sim[k]; }
        float inv = 1.f / den;
        #pragma unroll
        for (int k = 0; k < NPROTO; k++) sim[k] *= inv;

        // cand + gate
        float4 cand[4], rw[4];
        float gs = 0.f;
        #pragma unroll
        for (int j = 0; j < 4; j++) {
            float4 c = make_float4(0.f, 0.f, 0.f, 0.f);
            #pragma unroll
            for (int k = 0; k < NPROTO; k++) {
                float2 lo = unpack2(pkb[k][j * 2]), hi = unpack2(pkb[k][j * 2 + 1]);
                c.x += sim[k] * lo.x; c.y += sim[k] * lo.y;
                c.z += sim[k] * hi.x; c.w += sim[k] * hi.y;
            }
            c = c4(c, 5.f);
            cand[j] = c;
            float4 rv = c4(r4p[lane + 32 * j], 50.f);
            rw[j] = rv;
            float4 rc = c4(rv, 30.f);
            float4 wa = w4[lane + 32 * j];
            float4 wb = w4[128 + lane + 32 * j];
            gs += wa.x*rc.x + wa.y*rc.y + wa.z*rc.z + wa.w*rc.w;
            gs += wb.x*c.x  + wb.y*c.y  + wb.z*c.z  + wb.w*c.w;
        }
        {   // time contribution
            float4 tv = c4(reinterpret_cast<const float4*>(te)[(size_t)row * (TDIM/4) + lane], 30.f);
            float4 wc = w4[256 + lane];
            gs += wc.x*tv.x + wc.y*tv.y + wc.z*tv.z + wc.w*tv.w;
        }
        gs = wredsum(gs);
        float logit = clampf(gs + bg0, 10.f);
        float gg = 1.f / (1.f + __expf(-logit));

        // blend + LN2 + clip
        float4 up[4];
        s0 = 0.f; s1 = 0.f;
        #pragma unroll
        for (int j = 0; j < 4; j++) {
            float4 u;
            u.x = 0.8f * rw[j].x + 0.2f * ((1.f - gg) * rw[j].x + gg * cand[j].x);
            u.y = 0.8f * rw[j].y + 0.2f * ((1.f - gg) * rw[j].y + gg * cand[j].y);
            u.z = 0.8f * rw[j].z + 0.2f * ((1.f - gg) * rw[j].z + gg * cand[j].z);
            u.w = 0.8f * rw[j].w + 0.2f * ((1.f - gg) * rw[j].w + gg * cand[j].w);
            up[j] = u;
            s0 += u.x + u.y + u.z + u.w;
            s1 += u.x*u.x + u.y*u.y + u.z*u.z + u.w*u.w;
        }
        s0 = wredsum(s0); s1 = wredsum(s1);
        mean = s0 * (1.f / DDIM);
        rstd = rsqrtf(s1 * (1.f / DDIM) - mean * mean + 1e-6f);
        float4* o4 = reinterpret_cast<float4*>(out) + base4;
        #pragma unroll
        for (int j = 0; j < 4; j++) {
            float4 gm = g4[lane + 32 * j], bt = b4[lane + 32 * j];
            float4 o;
            o.x = clampf((up[j].x - mean) * rstd * gm.x + bt.x, 10.f);
            o.y = clampf((up[j].y - mean) * rstd * gm.y + bt.y, 10.f);
            o.z = clampf((up[j].z - mean) * rstd * gm.z + bt.z, 10.f);
            o.w = clampf((up[j].w - mean) * rstd * gm.w + bt.w, 10.f);
            o4[lane + 32 * j] = o;
        }
    }
}

// ---------------------------------------------------------------------------
extern "C" void kernel_launch(void* const* d_in, const int* in_sizes, int n_in,
                              void* d_out, int out_size) {
    (void)in_sizes; (void)n_in; (void)out_size;
    const float* raw  = (const float*)d_in[0];
    // d_in[1] = node_features: unused by the reference computation
    const float* edge = (const float*)d_in[2];
    const float* te   = (const float*)d_in[3];
    const float* prot = (const float*)d_in[4];
    const float* Wq   = (const float*)d_in[5];
    const float* bq   = (const float*)d_in[6];
    const float* Wg   = (const float*)d_in[7];
    const float* bg   = (const float*)d_in[8];
    const float* gam  = (const float*)d_in[9];
    const float* bet  = (const float*)d_in[10];
    const float* temp = (const float*)d_in[11];
    float* out = (float*)d_out;

    convB_kernel<<<(DDIM * KDIM / 4) / 256, 256>>>(Wq);
    cudaFuncSetAttribute(fused_kernel, cudaFuncAttributeMaxDynamicSharedMemorySize, FUSED_SMEM);
    fused_kernel<<<NROWS / BM, 512, FUSED_SMEM>>>(raw, edge, te, prot, bq, Wg, bg,
                                                  gam, bet, temp, out);
}